// round 1
// baseline (speedup 1.0000x reference)
#include <cuda_runtime.h>
#include <math.h>

// ---------------- problem constants ----------------
#define LSEQ   1024
#define BATCH  8
#define CDIM   256
#define DINNER 512
#define DSTATE 16
#define NROWS  (BATCH*LSEQ)   // 8192

// ---------------- scratch (static, no allocs) ----------------
__device__ float  g_xn   [(size_t)NROWS*CDIM];
__device__ float  g_xz   [(size_t)NROWS*1024];
__device__ float  g_u2   [(size_t)NROWS*DINNER];
__device__ float  g_dbc  [(size_t)NROWS*48];
__device__ float  g_dtlin[(size_t)NROWS*DINNER];
__device__ float4 g_dtuz [(size_t)NROWS*DINNER];
__device__ float2 g_bc   [(size_t)NROWS*DSTATE];
__device__ float  g_yg   [(size_t)NROWS*DINNER];
__device__ float  g_o    [(size_t)NROWS*CDIM];

// ---------------- LayerNorm + (B,C,H,W) -> (B,L,C) ----------------
// block = 256 thr handles (b, 32 consecutive l). smem transpose for coalescing.
__global__ __launch_bounds__(256) void ln_kernel(const float* __restrict__ x,
                                                 const float* __restrict__ gamma,
                                                 const float* __restrict__ beta) {
    __shared__ float sm[32*257];
    __shared__ float s_mu[32], s_rs[32];
    const int b  = blockIdx.x >> 5;
    const int l0 = (blockIdx.x & 31) * 32;
    const int t  = threadIdx.x;
    #pragma unroll
    for (int j = 0; j < 32; j++) {
        int e  = j*256 + t;
        int c  = e >> 5;
        int li = e & 31;
        sm[li*257 + c] = x[((size_t)(b*CDIM + c))*LSEQ + l0 + li];
    }
    __syncthreads();
    const int w = t >> 5, lane = t & 31;
    #pragma unroll
    for (int q = 0; q < 4; q++) {
        int li = w*4 + q;
        float s = 0.f, s2 = 0.f;
        #pragma unroll
        for (int j = 0; j < 8; j++) {
            float v = sm[li*257 + lane + j*32];
            s += v; s2 = fmaf(v, v, s2);
        }
        #pragma unroll
        for (int o = 16; o; o >>= 1) {
            s  += __shfl_xor_sync(0xffffffffu, s,  o);
            s2 += __shfl_xor_sync(0xffffffffu, s2, o);
        }
        if (lane == 0) {
            float mu  = s * (1.f/CDIM);
            float var = s2 * (1.f/CDIM) - mu*mu;
            s_mu[li] = mu;
            s_rs[li] = rsqrtf(var + 1e-5f);
        }
    }
    __syncthreads();
    const float g = gamma[t], be = beta[t];
    #pragma unroll
    for (int li = 0; li < 32; li++) {
        float v = (sm[li*257 + t] - s_mu[li]) * s_rs[li];
        g_xn[((size_t)(b*LSEQ + l0 + li))*CDIM + t] = fmaf(v, g, be);
    }
}

// ---------------- generic fp32 tiled GEMM: C = A(MxK) * B(KxN) ----------------
template<int BM, int BN, int BK, int TM, int TN>
__global__ __launch_bounds__(256) void gemm_kernel(const float* __restrict__ A,
                                                   const float* __restrict__ B,
                                                   float* __restrict__ C,
                                                   int M, int N, int K,
                                                   int lda, int ldb, int ldc) {
    __shared__ float As[BK][BM+4];
    __shared__ float Bs[BK][BN];
    const int tid = threadIdx.x;
    const int m0 = blockIdx.y * BM;
    const int n0 = blockIdx.x * BN;
    const int tx = tid % (BN/TN);
    const int ty = tid / (BN/TN);
    float acc[TM][TN] = {};
    constexpr int A_PER = (BM*BK/4)/256;
    constexpr int B_PER = (BK*BN/4)/256;

    for (int k0 = 0; k0 < K; k0 += BK) {
        #pragma unroll
        for (int i = 0; i < A_PER; i++) {
            int idx = tid + i*256;
            int row = idx / (BK/4);
            int kq  = idx % (BK/4);
            float4 v = *reinterpret_cast<const float4*>(&A[(size_t)(m0+row)*lda + k0 + kq*4]);
            As[kq*4+0][row] = v.x;
            As[kq*4+1][row] = v.y;
            As[kq*4+2][row] = v.z;
            As[kq*4+3][row] = v.w;
        }
        #pragma unroll
        for (int i = 0; i < B_PER; i++) {
            int idx  = tid + i*256;
            int krow = idx / (BN/4);
            int nq   = idx % (BN/4);
            int col  = n0 + nq*4;
            float4 v = make_float4(0.f,0.f,0.f,0.f);
            if (col < N) v = *reinterpret_cast<const float4*>(&B[(size_t)(k0+krow)*ldb + col]);
            *reinterpret_cast<float4*>(&Bs[krow][nq*4]) = v;
        }
        __syncthreads();
        #pragma unroll
        for (int k = 0; k < BK; k++) {
            float a[TM], bb[TN];
            #pragma unroll
            for (int i = 0; i < TM; i++) a[i]  = As[k][ty*TM+i];
            #pragma unroll
            for (int j = 0; j < TN; j++) bb[j] = Bs[k][tx*TN+j];
            #pragma unroll
            for (int i = 0; i < TM; i++)
                #pragma unroll
                for (int j = 0; j < TN; j++)
                    acc[i][j] = fmaf(a[i], bb[j], acc[i][j]);
        }
        __syncthreads();
    }
    #pragma unroll
    for (int i = 0; i < TM; i++) {
        int row = m0 + ty*TM + i;
        #pragma unroll
        for (int j = 0; j < TN; j += 4) {
            int col = n0 + tx*TN + j;
            if (col < N) {
                float4 v = make_float4(acc[i][j], acc[i][j+1], acc[i][j+2], acc[i][j+3]);
                *reinterpret_cast<float4*>(&C[(size_t)row*ldc + col]) = v;
            }
        }
    }
}

// ---------------- depthwise causal conv (D_CONV=4) + SiLU ----------------
__global__ __launch_bounds__(256) void conv_silu_kernel(const float* __restrict__ cw,
                                                        const float* __restrict__ cb) {
    int gid = blockIdx.x*256 + threadIdx.x;   // over NROWS*DINNER
    int d   = gid & (DINNER-1);
    int row = gid >> 9;
    int l   = row & (LSEQ-1);
    float acc = cb[d];
    #pragma unroll
    for (int k = 0; k < 4; k++) {
        int ll = l - 3 + k;
        if (ll >= 0)
            acc = fmaf(g_xz[((size_t)(row - 3 + k))*1024 + d], cw[d*4+k], acc);
    }
    g_u2[gid] = acc / (1.f + __expf(-acc));
}

// ---------------- pack (dt,u2,z) as float4, with softplus(dt)+bias ----------------
__global__ __launch_bounds__(256) void pack_dtuz_kernel(const float* __restrict__ bdt) {
    int gid = blockIdx.x*256 + threadIdx.x;   // over NROWS*DINNER
    int d   = gid & (DINNER-1);
    int row = gid >> 9;
    float xl  = g_dtlin[gid] + bdt[d];
    float dtv = (xl > 20.f) ? xl : log1pf(__expf(xl));
    float u2v = g_u2[gid];
    float z   = g_xz[(size_t)row*1024 + DINNER + d];
    g_dtuz[gid] = make_float4(dtv, u2v, z, 0.f);
}

// ---------------- pack (B,C) as float2 ----------------
__global__ __launch_bounds__(256) void pack_bc_kernel() {
    int gid = blockIdx.x*256 + threadIdx.x;   // over NROWS*DSTATE
    int s   = gid & 15;
    int row = gid >> 4;
    g_bc[gid] = make_float2(g_dbc[row*48 + 16 + s], g_dbc[row*48 + 32 + s]);
}

// ---------------- selective scan: warp = 2 channels, lane-per-state ----------------
__global__ __launch_bounds__(256) void scan_kernel(const float* __restrict__ A_log,
                                                   const float* __restrict__ D_skip) {
    int gw   = (blockIdx.x * 256 + threadIdx.x) >> 5;   // 0..2047
    int lane = threadIdx.x & 31;
    int b    = gw >> 8;
    int pair = gw & 255;
    int d    = pair*2 + (lane >> 4);
    int s    = lane & 15;
    float Aval = -__expf(A_log[d*DSTATE + s]);
    float Dd   = D_skip[d];
    size_t rowbase = (size_t)b * LSEQ;
    const float4* duP = g_dtuz + rowbase*DINNER + d;
    const float2* bcP = g_bc   + rowbase*DSTATE + s;
    float*        ygP = g_yg   + rowbase*DINNER + d;
    float h = 0.f;
    for (int l = 0; l < LSEQ; l++) {
        float4 du  = duP[(size_t)l*DINNER];
        float2 bcv = bcP[(size_t)l*DSTATE];
        float dA = __expf(du.x * Aval);
        h = fmaf(dA, h, du.x * du.y * bcv.x);
        float p = h * bcv.y;
        p += __shfl_xor_sync(0xffffffffu, p, 8);
        p += __shfl_xor_sync(0xffffffffu, p, 4);
        p += __shfl_xor_sync(0xffffffffu, p, 2);
        p += __shfl_xor_sync(0xffffffffu, p, 1);
        if (s == 0) {
            float yv = p + du.y * Dd;
            float sz = du.z / (1.f + __expf(-du.z));
            ygP[(size_t)l*DINNER] = yv * sz;
        }
    }
}

// ---------------- o(B,L,C) -> out(B,C,H,W) + residual x ----------------
__global__ __launch_bounds__(256) void out_kernel(const float* __restrict__ x,
                                                  float* __restrict__ out) {
    __shared__ float sm[32][33];
    const int b  = blockIdx.z;
    const int c0 = blockIdx.y * 32;
    const int l0 = blockIdx.x * 32;
    const int t  = threadIdx.x;
    const int ci = t & 31, lq = t >> 5;
    #pragma unroll
    for (int p = 0; p < 4; p++) {
        int li = p*8 + lq;
        sm[li][ci] = g_o[((size_t)(b*LSEQ + l0 + li))*CDIM + c0 + ci];
    }
    __syncthreads();
    const int li2 = t & 31, cq = t >> 5;
    #pragma unroll
    for (int p = 0; p < 4; p++) {
        int ci2 = p*8 + cq;
        size_t idx = ((size_t)(b*CDIM + c0 + ci2))*LSEQ + l0 + li2;
        out[idx] = sm[li2][ci2] + x[idx];
    }
}

// ---------------- host launch ----------------
extern "C" void kernel_launch(void* const* d_in, const int* in_sizes, int n_in,
                              void* d_out, int out_size) {
    const float* x       = (const float*)d_in[0];
    const float* ln_g    = (const float*)d_in[1];
    const float* ln_b    = (const float*)d_in[2];
    const float* W_in    = (const float*)d_in[3];
    const float* conv_w  = (const float*)d_in[4];
    const float* conv_b  = (const float*)d_in[5];
    const float* W_xproj = (const float*)d_in[6];
    const float* W_dt    = (const float*)d_in[7];
    const float* b_dt    = (const float*)d_in[8];
    const float* A_log   = (const float*)d_in[9];
    const float* D_skip  = (const float*)d_in[10];
    const float* W_out   = (const float*)d_in[11];
    float* out = (float*)d_out;

    float  *p_xn, *p_xz, *p_u2, *p_dbc, *p_dtlin, *p_yg, *p_o;
    cudaGetSymbolAddress((void**)&p_xn,    g_xn);
    cudaGetSymbolAddress((void**)&p_xz,    g_xz);
    cudaGetSymbolAddress((void**)&p_u2,    g_u2);
    cudaGetSymbolAddress((void**)&p_dbc,   g_dbc);
    cudaGetSymbolAddress((void**)&p_dtlin, g_dtlin);
    cudaGetSymbolAddress((void**)&p_yg,    g_yg);
    cudaGetSymbolAddress((void**)&p_o,     g_o);

    // 1. LayerNorm + layout
    ln_kernel<<<BATCH*32, 256>>>(x, ln_g, ln_b);

    // 2. xz = xn @ W_in  (8192x256x1024)
    gemm_kernel<128,128,16,8,8><<<dim3(1024/128, NROWS/128), 256>>>(
        p_xn, W_in, p_xz, NROWS, 1024, CDIM, CDIM, 1024, 1024);

    // 3. depthwise conv + silu -> u2
    conv_silu_kernel<<<(NROWS*DINNER)/256, 256>>>(conv_w, conv_b);

    // 4. dbc = u2 @ W_xproj  (8192x512x48)
    gemm_kernel<64,64,16,4,4><<<dim3(1, NROWS/64), 256>>>(
        p_u2, W_xproj, p_dbc, NROWS, 48, DINNER, DINNER, 48, 48);

    // 5. dtlin = dbc[:, :16] @ W_dt  (8192x16x512)
    gemm_kernel<128,128,16,8,8><<<dim3(512/128, NROWS/128), 256>>>(
        p_dbc, W_dt, p_dtlin, NROWS, DINNER, 16, 48, DINNER, DINNER);

    // 6. pack scan operands
    pack_dtuz_kernel<<<(NROWS*DINNER)/256, 256>>>(b_dt);
    pack_bc_kernel<<<(NROWS*DSTATE)/256, 256>>>();

    // 7. selective scan + skip + gate -> yg
    scan_kernel<<<256, 256>>>(A_log, D_skip);

    // 8. o = yg @ W_out  (8192x512x256)
    gemm_kernel<128,128,16,8,8><<<dim3(256/128, NROWS/128), 256>>>(
        p_yg, W_out, p_o, NROWS, CDIM, DINNER, DINNER, CDIM, CDIM);

    // 9. transpose + residual
    out_kernel<<<dim3(32, 8, 8), 256>>>(x, out);
}

// round 2
// speedup vs baseline: 1.3294x; 1.3294x over previous
#include <cuda_runtime.h>
#include <math.h>
#include <stdint.h>

// ---------------- problem constants ----------------
#define LSEQ   1024
#define BATCH  8
#define CDIM   256
#define DINNER 512
#define DSTATE 16
#define NROWS  (BATCH*LSEQ)   // 8192

// ---------------- scratch (static, no allocs) ----------------
__device__ float  g_xn   [(size_t)NROWS*CDIM];
__device__ float  g_u    [(size_t)NROWS*DINNER];   // raw u (pre-conv)
__device__ float  g_gz   [(size_t)NROWS*DINNER];   // silu(z)
__device__ float  g_u2   [(size_t)NROWS*DINNER];   // post conv+silu
__device__ float  g_wcomb[(size_t)DINNER*DINNER];  // W_xproj[:, :16] @ W_dt
__device__ float2 g_du   [(size_t)NROWS*DINNER];   // (dt, u2) packed
__device__ float2 g_bc   [(size_t)NROWS*DSTATE];   // (B_s, C_s) packed
__device__ float  g_yg   [(size_t)NROWS*DINNER];   // y * silu(z)
__device__ float  g_o    [(size_t)NROWS*CDIM];

// ---------------- helpers ----------------
__device__ __forceinline__ uint32_t f2tf(float v) {
    uint32_t r; asm("cvt.rna.tf32.f32 %0, %1;" : "=r"(r) : "f"(v)); return r;
}
__device__ __forceinline__ void mma8(float* c, const uint32_t* a, const uint32_t* b) {
    asm volatile(
        "mma.sync.aligned.m16n8k8.row.col.f32.tf32.tf32.f32 "
        "{%0,%1,%2,%3}, {%4,%5,%6,%7}, {%8,%9}, {%0,%1,%2,%3};\n"
        : "+f"(c[0]), "+f"(c[1]), "+f"(c[2]), "+f"(c[3])
        : "r"(a[0]), "r"(a[1]), "r"(a[2]), "r"(a[3]), "r"(b[0]), "r"(b[1]));
}
__device__ __forceinline__ float siluf(float v) { return v / (1.f + __expf(-v)); }
__device__ __forceinline__ float softplusf(float v) {
    return (v > 20.f) ? v : log1pf(__expf(v));
}

// ---------------- LayerNorm + (B,C,H,W) -> (B,L,C) ----------------
__global__ __launch_bounds__(256) void ln_kernel(const float* __restrict__ x,
                                                 const float* __restrict__ gamma,
                                                 const float* __restrict__ beta) {
    __shared__ float sm[32*257];
    __shared__ float s_mu[32], s_rs[32];
    const int b  = blockIdx.x >> 5;
    const int l0 = (blockIdx.x & 31) * 32;
    const int t  = threadIdx.x;
    #pragma unroll
    for (int j = 0; j < 32; j++) {
        int e  = j*256 + t;
        int c  = e >> 5;
        int li = e & 31;
        sm[li*257 + c] = x[((size_t)(b*CDIM + c))*LSEQ + l0 + li];
    }
    __syncthreads();
    const int w = t >> 5, lane = t & 31;
    #pragma unroll
    for (int q = 0; q < 4; q++) {
        int li = w*4 + q;
        float s = 0.f, s2 = 0.f;
        #pragma unroll
        for (int j = 0; j < 8; j++) {
            float v = sm[li*257 + lane + j*32];
            s += v; s2 = fmaf(v, v, s2);
        }
        #pragma unroll
        for (int o = 16; o; o >>= 1) {
            s  += __shfl_xor_sync(0xffffffffu, s,  o);
            s2 += __shfl_xor_sync(0xffffffffu, s2, o);
        }
        if (lane == 0) {
            float mu  = s * (1.f/CDIM);
            float var = s2 * (1.f/CDIM) - mu*mu;
            s_mu[li] = mu;
            s_rs[li] = rsqrtf(var + 1e-5f);
        }
    }
    __syncthreads();
    const float g = gamma[t], be = beta[t];
    #pragma unroll
    for (int li = 0; li < 32; li++) {
        float v = (sm[li*257 + t] - s_mu[li]) * s_rs[li];
        g_xn[((size_t)(b*LSEQ + l0 + li))*CDIM + t] = fmaf(v, g, be);
    }
}

// ---------------- W_comb = W_xproj[:, :16] @ W_dt  (512x512) ----------------
__global__ __launch_bounds__(256) void wcomb_kernel(const float* __restrict__ Wx,
                                                    const float* __restrict__ Wdt) {
    __shared__ float wx[16];
    int r = blockIdx.x;
    if (threadIdx.x < 16) wx[threadIdx.x] = Wx[r*48 + threadIdx.x];
    __syncthreads();
    for (int c = threadIdx.x; c < DINNER; c += 256) {
        float a = 0.f;
        #pragma unroll
        for (int t = 0; t < 16; t++) a = fmaf(wx[t], Wdt[t*DINNER + c], a);
        g_wcomb[(size_t)r*DINNER + c] = a;
    }
}

// ---------------- tf32 tensor-core GEMM with fused epilogues ----------------
// MODE 0: plain C[M,N]            (C, ldc)
// MODE 1: split u/z + silu(z)     (C = g_u, Caux = g_gz; global N=1024)
// MODE 2: dt pack: softplus(v+b_dt) paired with u2 -> float2 (dt,u2)
//         (C = (float*)g_du, e0 = b_dt, e1 = g_u2)
// MODE 3: bc pack: cols 0..15 = B, 16..31 = C -> interleave (B_s,C_s)
//         (C = (float*)g_bc)  requires BN=32, WN=32
template<int BM, int BN, int WM, int WN, int MODE>
__global__ __launch_bounds__(256) void gemm_tc(
    const float* __restrict__ A, const float* __restrict__ B,
    float* __restrict__ C, float* __restrict__ Caux,
    const float* __restrict__ e0, const float* __restrict__ e1,
    int K, int lda, int ldb, int ldc)
{
    constexpr int BK = 32;
    constexpr int LDA_S = BK + 4;     // As[BM][36] floats
    constexpr int LDB_S = BN + 8;     // Bs[BK][BN+8]
    __shared__ uint32_t As[BM * LDA_S];
    __shared__ uint32_t Bs[BK * LDB_S];
    const int tid  = threadIdx.x;
    const int wid  = tid >> 5, lane = tid & 31;
    const int g    = lane >> 2, q = lane & 3;
    constexpr int NWN = BN / WN;
    const int wm = wid / NWN, wn = wid % NWN;
    const int m0 = blockIdx.y * BM, n0 = blockIdx.x * BN;
    constexpr int MF = WM / 16, NF = WN / 8;
    float acc[MF][NF][4] = {};
    constexpr int A_PER = BM*BK/(4*256);
    constexpr int B_PER = BK*BN/(4*256);
    float4 ra[A_PER], rb[B_PER];

    auto ldg_tile = [&](int k0) {
        #pragma unroll
        for (int i = 0; i < A_PER; i++) {
            int idx = tid + i*256;
            int row = idx / (BK/4), kq = idx % (BK/4);
            ra[i] = *(const float4*)&A[(size_t)(m0+row)*lda + k0 + kq*4];
        }
        #pragma unroll
        for (int i = 0; i < B_PER; i++) {
            int idx = tid + i*256;
            int kr = idx / (BN/4), nq = idx % (BN/4);
            rb[i] = *(const float4*)&B[(size_t)(k0+kr)*ldb + n0 + nq*4];
        }
    };
    auto sts_tile = [&]() {
        #pragma unroll
        for (int i = 0; i < A_PER; i++) {
            int idx = tid + i*256;
            int row = idx / (BK/4), kq = idx % (BK/4);
            uint4 v = make_uint4(f2tf(ra[i].x), f2tf(ra[i].y), f2tf(ra[i].z), f2tf(ra[i].w));
            *(uint4*)&As[row*LDA_S + kq*4] = v;
        }
        #pragma unroll
        for (int i = 0; i < B_PER; i++) {
            int idx = tid + i*256;
            int kr = idx / (BN/4), nq = idx % (BN/4);
            uint4 v = make_uint4(f2tf(rb[i].x), f2tf(rb[i].y), f2tf(rb[i].z), f2tf(rb[i].w));
            *(uint4*)&Bs[kr*LDB_S + nq*4] = v;
        }
    };
    auto compute = [&]() {
        #pragma unroll
        for (int ko = 0; ko < BK; ko += 8) {
            uint32_t af[MF][4];
            #pragma unroll
            for (int i = 0; i < MF; i++) {
                int r = wm*WM + i*16 + g;
                af[i][0] = As[(r  )*LDA_S + ko + q];
                af[i][1] = As[(r+8)*LDA_S + ko + q];
                af[i][2] = As[(r  )*LDA_S + ko + q + 4];
                af[i][3] = As[(r+8)*LDA_S + ko + q + 4];
            }
            uint32_t bf[NF][2];
            #pragma unroll
            for (int j = 0; j < NF; j++) {
                int c = wn*WN + j*8 + g;
                bf[j][0] = Bs[(ko+q  )*LDB_S + c];
                bf[j][1] = Bs[(ko+q+4)*LDB_S + c];
            }
            #pragma unroll
            for (int i = 0; i < MF; i++)
                #pragma unroll
                for (int j = 0; j < NF; j++)
                    mma8(acc[i][j], af[i], bf[j]);
        }
    };

    ldg_tile(0);
    sts_tile();
    __syncthreads();
    #pragma unroll 1
    for (int k0 = BK; k0 < K; k0 += BK) {
        ldg_tile(k0);
        compute();
        __syncthreads();
        sts_tile();
        __syncthreads();
    }
    compute();

    // ----- epilogue -----
    #pragma unroll
    for (int i = 0; i < MF; i++) {
        int row = m0 + wm*WM + i*16 + g;
        if (MODE == 3) {
            // BN=32, WN=32 (wn==0): pair col s with s+16
            #pragma unroll
            for (int j = 0; j < 2; j++) {
                int s = j*8 + 2*q;
                float4 lo = make_float4(acc[i][j][0], acc[i][j+2][0],
                                        acc[i][j][1], acc[i][j+2][1]);
                float4 hi = make_float4(acc[i][j][2], acc[i][j+2][2],
                                        acc[i][j][3], acc[i][j+2][3]);
                *(float4*)&C[((size_t)(row  )*DSTATE + s)*2] = lo;
                *(float4*)&C[((size_t)(row+8)*DSTATE + s)*2] = hi;
            }
        } else {
            #pragma unroll
            for (int j = 0; j < NF; j++) {
                int col = n0 + wn*WN + j*8 + 2*q;
                float v0 = acc[i][j][0], v1 = acc[i][j][1];
                float v2 = acc[i][j][2], v3 = acc[i][j][3];
                if (MODE == 0) {
                    *(float2*)&C[(size_t)(row  )*ldc + col] = make_float2(v0, v1);
                    *(float2*)&C[(size_t)(row+8)*ldc + col] = make_float2(v2, v3);
                } else if (MODE == 1) {
                    if (col < DINNER) {
                        *(float2*)&C[(size_t)(row  )*DINNER + col] = make_float2(v0, v1);
                        *(float2*)&C[(size_t)(row+8)*DINNER + col] = make_float2(v2, v3);
                    } else {
                        int cz = col - DINNER;
                        *(float2*)&Caux[(size_t)(row  )*DINNER + cz] =
                            make_float2(siluf(v0), siluf(v1));
                        *(float2*)&Caux[(size_t)(row+8)*DINNER + cz] =
                            make_float2(siluf(v2), siluf(v3));
                    }
                } else { // MODE 2
                    float bd0 = e0[col], bd1 = e0[col+1];
                    float2 ua = *(const float2*)&e1[(size_t)(row  )*DINNER + col];
                    float2 ub = *(const float2*)&e1[(size_t)(row+8)*DINNER + col];
                    float4 oa = make_float4(softplusf(v0 + bd0), ua.x,
                                            softplusf(v1 + bd1), ua.y);
                    float4 ob = make_float4(softplusf(v2 + bd0), ub.x,
                                            softplusf(v3 + bd1), ub.y);
                    *(float4*)&C[((size_t)(row  )*DINNER + col)*2] = oa;
                    *(float4*)&C[((size_t)(row+8)*DINNER + col)*2] = ob;
                }
            }
        }
    }
}

// ---------------- depthwise causal conv (D_CONV=4) + SiLU ----------------
__global__ __launch_bounds__(256) void conv_silu_kernel(const float* __restrict__ cw,
                                                        const float* __restrict__ cb) {
    int gid = blockIdx.x*256 + threadIdx.x;   // over NROWS*DINNER
    int d   = gid & (DINNER-1);
    int row = gid >> 9;
    int l   = row & (LSEQ-1);
    float acc = cb[d];
    #pragma unroll
    for (int k = 0; k < 4; k++) {
        int ll = l - 3 + k;
        if (ll >= 0)
            acc = fmaf(g_u[((size_t)(row - 3 + k))*DINNER + d], cw[d*4+k], acc);
    }
    g_u2[gid] = siluf(acc);
}

// ---------------- selective scan: warp = 2 channels, lane-per-state ----------------
__global__ __launch_bounds__(256) void scan_kernel(const float* __restrict__ A_log,
                                                   const float* __restrict__ D_skip) {
    int gw   = (blockIdx.x * 256 + threadIdx.x) >> 5;   // 0..2047
    int lane = threadIdx.x & 31;
    int b    = gw >> 8;
    int pair = gw & 255;
    int d    = pair*2 + (lane >> 4);
    int s    = lane & 15;
    float Aval = -__expf(A_log[d*DSTATE + s]);
    float Dd   = D_skip[d];
    size_t rb = (size_t)b * LSEQ;
    const float2* duP = g_du + rb*DINNER + d;
    const float2* bcP = g_bc + rb*DSTATE + s;
    const float*  gzP = g_gz + rb*DINNER + d;
    float*        ygP = g_yg + rb*DINNER + d;
    float h = 0.f;
    for (int l = 0; l < LSEQ; l++) {
        float2 du  = duP[(size_t)l*DINNER];
        float2 bcv = bcP[(size_t)l*DSTATE];
        float dA = __expf(du.x * Aval);
        h = fmaf(dA, h, du.x * du.y * bcv.x);
        float p = h * bcv.y;
        p += __shfl_xor_sync(0xffffffffu, p, 8);
        p += __shfl_xor_sync(0xffffffffu, p, 4);
        p += __shfl_xor_sync(0xffffffffu, p, 2);
        p += __shfl_xor_sync(0xffffffffu, p, 1);
        if (s == 0) {
            float yv = p + du.y * Dd;
            ygP[(size_t)l*DINNER] = yv * gzP[(size_t)l*DINNER];
        }
    }
}

// ---------------- o(B,L,C) -> out(B,C,H,W) + residual x ----------------
__global__ __launch_bounds__(256) void out_kernel(const float* __restrict__ x,
                                                  float* __restrict__ out) {
    __shared__ float sm[32][33];
    const int b  = blockIdx.z;
    const int c0 = blockIdx.y * 32;
    const int l0 = blockIdx.x * 32;
    const int t  = threadIdx.x;
    const int ci = t & 31, lq = t >> 5;
    #pragma unroll
    for (int p = 0; p < 4; p++) {
        int li = p*8 + lq;
        sm[li][ci] = g_o[((size_t)(b*LSEQ + l0 + li))*CDIM + c0 + ci];
    }
    __syncthreads();
    const int li2 = t & 31, cq = t >> 5;
    #pragma unroll
    for (int p = 0; p < 4; p++) {
        int ci2 = p*8 + cq;
        size_t idx = ((size_t)(b*CDIM + c0 + ci2))*LSEQ + l0 + li2;
        out[idx] = sm[li2][ci2] + x[idx];
    }
}

// ---------------- host launch ----------------
extern "C" void kernel_launch(void* const* d_in, const int* in_sizes, int n_in,
                              void* d_out, int out_size) {
    const float* x       = (const float*)d_in[0];
    const float* ln_g    = (const float*)d_in[1];
    const float* ln_b    = (const float*)d_in[2];
    const float* W_in    = (const float*)d_in[3];
    const float* conv_w  = (const float*)d_in[4];
    const float* conv_b  = (const float*)d_in[5];
    const float* W_xproj = (const float*)d_in[6];
    const float* W_dt    = (const float*)d_in[7];
    const float* b_dt    = (const float*)d_in[8];
    const float* A_log   = (const float*)d_in[9];
    const float* D_skip  = (const float*)d_in[10];
    const float* W_out   = (const float*)d_in[11];
    float* out = (float*)d_out;

    float *p_xn, *p_u, *p_gz, *p_u2, *p_wcomb, *p_yg, *p_o;
    float2 *p_du, *p_bc;
    cudaGetSymbolAddress((void**)&p_xn,    g_xn);
    cudaGetSymbolAddress((void**)&p_u,     g_u);
    cudaGetSymbolAddress((void**)&p_gz,    g_gz);
    cudaGetSymbolAddress((void**)&p_u2,    g_u2);
    cudaGetSymbolAddress((void**)&p_wcomb, g_wcomb);
    cudaGetSymbolAddress((void**)&p_du,    g_du);
    cudaGetSymbolAddress((void**)&p_bc,    g_bc);
    cudaGetSymbolAddress((void**)&p_yg,    g_yg);
    cudaGetSymbolAddress((void**)&p_o,     g_o);

    // 1. LayerNorm + layout
    ln_kernel<<<BATCH*32, 256>>>(x, ln_g, ln_b);

    // 1b. W_comb = W_xproj[:, :16] @ W_dt
    wcomb_kernel<<<DINNER, 256>>>(W_xproj, W_dt);

    // 2. xz = xn @ W_in (8192 x 1024 x 256), split u / silu(z)
    gemm_tc<128,64,32,32,1><<<dim3(1024/64, NROWS/128), 256>>>(
        p_xn, W_in, p_u, p_gz, nullptr, nullptr, CDIM, CDIM, 1024, 0);

    // 3. depthwise conv + silu -> u2
    conv_silu_kernel<<<(NROWS*DINNER)/256, 256>>>(conv_w, conv_b);

    // 4. dtlin = u2 @ W_comb (8192 x 512 x 512), fused softplus + (dt,u2) pack
    gemm_tc<128,64,32,32,2><<<dim3(DINNER/64, NROWS/128), 256>>>(
        p_u2, p_wcomb, (float*)p_du, nullptr, b_dt, p_u2, DINNER, DINNER, DINNER, 0);

    // 5. bc = u2 @ W_xproj[:, 16:48] (8192 x 32 x 512), fused (B,C) pack
    gemm_tc<128,32,16,32,3><<<dim3(1, NROWS/128), 256>>>(
        p_u2, W_xproj + 16, (float*)p_bc, nullptr, nullptr, nullptr,
        DINNER, DINNER, 48, 0);

    // 6. selective scan + skip + gate -> yg
    scan_kernel<<<256, 256>>>(A_log, D_skip);

    // 7. o = yg @ W_out (8192 x 256 x 512)
    gemm_tc<128,64,32,32,0><<<dim3(CDIM/64, NROWS/128), 256>>>(
        p_yg, W_out, p_o, nullptr, nullptr, nullptr, DINNER, DINNER, CDIM, CDIM);

    // 8. transpose + residual
    out_kernel<<<dim3(32, 8, 8), 256>>>(x, out);
}